// round 15
// baseline (speedup 1.0000x reference)
#include <cuda_runtime.h>
#include <math.h>

#define N_IMG 32
#define ROWS_PER_IMG 262144              // 128*128*64 / 4 float4-rows per image
#define IMGS_PER_GROUP 16                // 64 MiB per group = half of L2
#define N_GROUPS (N_IMG / IMGS_PER_GROUP)
#define K1_CTAS_PER_IMG 64
#define K1_THREADS 256
#define ROWS_PER_CTA (ROWS_PER_IMG / K1_CTAS_PER_IMG)   // 4096
#define ROWS_PER_THREAD (ROWS_PER_CTA / K1_THREADS)     // 16
#define K1_BATCH 8

// Deterministic scratch (no device allocation allowed).
__device__ float g_part[N_IMG][K1_CTAS_PER_IMG][14];
__device__ float g_coef[N_IMG][8];   // w0..w3, b, pad

// ---------------------------------------------------------------------------
// K1g: per-image raw moments for one 16-image group. Body identical to the
// proven 25.6us/5.4TB/s config (plain __ldg float4, batch-8, 16 rows/thr).
// ---------------------------------------------------------------------------
__global__ void __launch_bounds__(K1_THREADS)
k1_group(const float4* __restrict__ in, int base_img) {
    const int img = base_img + (blockIdx.x >> 6);
    const int cta = blockIdx.x & 63;
    const float4* p = in + (size_t)img * ROWS_PER_IMG + cta * ROWS_PER_CTA + threadIdx.x;

    float s0 = 0.f, s1 = 0.f, s2 = 0.f, s3 = 0.f;
    float q00 = 0.f, q01 = 0.f, q02 = 0.f, q03 = 0.f;
    float q11 = 0.f, q12 = 0.f, q13 = 0.f;
    float q22 = 0.f, q23 = 0.f, q33 = 0.f;

#pragma unroll
    for (int g = 0; g < ROWS_PER_THREAD / K1_BATCH; g++) {
        float4 buf[K1_BATCH];
#pragma unroll
        for (int j = 0; j < K1_BATCH; j++)
            buf[j] = __ldg(p + (g * K1_BATCH + j) * K1_THREADS);
#pragma unroll
        for (int j = 0; j < K1_BATCH; j++) {
            float4 v = buf[j];
            s0 += v.x; s1 += v.y; s2 += v.z; s3 += v.w;
            q00 = fmaf(v.x, v.x, q00); q01 = fmaf(v.x, v.y, q01);
            q02 = fmaf(v.x, v.z, q02); q03 = fmaf(v.x, v.w, q03);
            q11 = fmaf(v.y, v.y, q11); q12 = fmaf(v.y, v.z, q12);
            q13 = fmaf(v.y, v.w, q13);
            q22 = fmaf(v.z, v.z, q22); q23 = fmaf(v.z, v.w, q23);
            q33 = fmaf(v.w, v.w, q33);
        }
    }

    float vals[14] = {s0, s1, s2, s3, q00, q01, q02, q03, q11, q12, q13, q22, q23, q33};

    __shared__ float sm[8][14];
    const int lane = threadIdx.x & 31;
    const int warp = threadIdx.x >> 5;

#pragma unroll
    for (int i = 0; i < 14; i++) {
        float v = vals[i];
#pragma unroll
        for (int off = 16; off; off >>= 1)
            v += __shfl_down_sync(0xffffffffu, v, off);
        if (lane == 0) sm[warp][i] = v;
    }
    __syncthreads();
    if (warp == 0 && lane < 14) {
        float v = 0.f;
#pragma unroll
        for (int w = 0; w < 8; w++) v += sm[w][lane];
        g_part[img][cta][lane] = v;
    }
}

// ---------------------------------------------------------------------------
// K2g: final reduction (fp64) + stats + shifted-gram fp32 Jacobi for the
// group's 16 images. Unchanged math from the verified solver.
// ---------------------------------------------------------------------------
__global__ void k2_group(int base_img) {
    const int img = base_img + blockIdx.x;
    const int t = threadIdx.x;
    __shared__ double red[14];

    if (t < 14) {
        double acc = 0.0;
#pragma unroll 4
        for (int c = 0; c < K1_CTAS_PER_IMG; c++)
            acc += (double)g_part[img][c][t];
        red[t] = acc;
    }
    __syncthreads();

    if (t == 0) {
        const double N = (double)ROWS_PER_IMG;
        double S[4] = {red[0], red[1], red[2], red[3]};
        double Q[4][4];
        Q[0][0] = red[4];  Q[0][1] = red[5];  Q[0][2] = red[6];  Q[0][3] = red[7];
        Q[1][1] = red[8];  Q[1][2] = red[9];  Q[1][3] = red[10];
        Q[2][2] = red[11]; Q[2][3] = red[12]; Q[3][3] = red[13];
        Q[1][0] = Q[0][1]; Q[2][0] = Q[0][2]; Q[3][0] = Q[0][3];
        Q[2][1] = Q[1][2]; Q[3][1] = Q[1][3]; Q[3][2] = Q[2][3];

        double mu[4], inv[4];
        bool zerov[4];
#pragma unroll
        for (int i = 0; i < 4; i++) {
            mu[i] = S[i] / N;
            double var = Q[i][i] / N - mu[i] * mu[i];
            if (var < 0.0) var = 0.0;
            double sd = sqrt(var);
            zerov[i] = (sd == 0.0);
            inv[i] = zerov[i] ? 0.0 : 1.0 / sd;
        }

        float A[4][4];
        for (int i = 0; i < 4; i++)
            for (int j = 0; j < 4; j++) {
                double g = (Q[i][j] - N * mu[i] * mu[j]) * inv[i] * inv[j];
                if (i == j) g = zerov[i] ? -N : 0.0;
                A[i][j] = (float)g;
            }

        float V[4][4] = {{1,0,0,0},{0,1,0,0},{0,0,1,0},{0,0,0,1}};
        for (int sweep = 0; sweep < 8; sweep++) {
            float off = fabsf(A[0][1]) + fabsf(A[0][2]) + fabsf(A[0][3])
                      + fabsf(A[1][2]) + fabsf(A[1][3]) + fabsf(A[2][3]);
            if (off < 1e-3f) break;   // entries O(500); fp32 noise floor
            for (int p = 0; p < 3; p++) {
                for (int q = p + 1; q < 4; q++) {
                    float apq = A[p][q];
                    if (fabsf(apq) == 0.0f) continue;
                    float theta = (A[q][q] - A[p][p]) / (2.0f * apq);
                    float tt = ((theta >= 0.0f) ? 1.0f : -1.0f)
                             / (fabsf(theta) + sqrtf(theta * theta + 1.0f));
                    float c = rsqrtf(tt * tt + 1.0f);
                    float s = tt * c;
                    for (int k = 0; k < 4; k++) {
                        float akp = A[k][p], akq = A[k][q];
                        A[k][p] = c * akp - s * akq;
                        A[k][q] = s * akp + c * akq;
                    }
                    for (int k = 0; k < 4; k++) {
                        float apk = A[p][k], aqk = A[q][k];
                        A[p][k] = c * apk - s * aqk;
                        A[q][k] = s * apk + c * aqk;
                    }
                    for (int k = 0; k < 4; k++) {
                        float vkp = V[k][p], vkq = V[k][q];
                        V[k][p] = c * vkp - s * vkq;
                        V[k][q] = s * vkp + c * vkq;
                    }
                }
            }
        }

        int best = 0;
        for (int i = 1; i < 4; i++)
            if (A[i][i] > A[best][best]) best = i;

        float v[4]; float sum = 0.0f;
#pragma unroll
        for (int i = 0; i < 4; i++) { v[i] = V[i][best]; sum += v[i]; }
        double sgn = (sum < 0.0f) ? -1.0 : 1.0;

        double b = 0.0;
#pragma unroll
        for (int i = 0; i < 4; i++) {
            double wi = sgn * (double)v[i] * inv[i];
            g_coef[img][i] = (float)wi;
            b -= wi * mu[i];
        }
        g_coef[img][4] = (float)b;
    }
}

// ---------------------------------------------------------------------------
// K3g: projection of one 16-image group. The group's 64 MiB was streamed
// through L2 by k1_group with only k2_group's few KB intervening, and 64 MiB
// is half of the 126 MB L2 -> reads should be L2 hits. Proven 4-outputs-per-
// thread body (4 independent LDG.128 -> one STG.128 streaming store; __stcs
// keeps the 8 MiB write stream from evicting the pinned group).
// ---------------------------------------------------------------------------
__global__ void __launch_bounds__(256)
k3_group(const float4* __restrict__ in, float4* __restrict__ out, int base_img) {
    const int o4g = blockIdx.x * 256 + threadIdx.x;    // float4 idx within group
    const int img = base_img + (o4g >> 16);            // 65536 float4-out / image
    const int lo4 = o4g & 65535;
    const int S  = lo4 >> 4;           // 16 float4 per (h2,w2) block
    const int c4 = lo4 & 15;
    const int h2 = S >> 6, w2i = S & 63;
    const int pp = c4 >> 2;            // ph*2 + pw (4 c_out share a patch pos)
    const int cgb = (c4 & 3) << 2;     // base channel-group 0,4,8,12
    const int ph = pp >> 1, pw = pp & 1;
    const int m = (((h2 << 1) + ph) * 128 + ((w2i << 1) + pw)) * 16 + cgb;

    const float4* src = in + (size_t)img * ROWS_PER_IMG + m;
    float4 x0 = __ldg(src + 0);
    float4 x1 = __ldg(src + 1);
    float4 x2 = __ldg(src + 2);
    float4 x3 = __ldg(src + 3);

    const float* cf = g_coef[img];
    const float w0 = cf[0], w1 = cf[1], w2c = cf[2], w3 = cf[3], b = cf[4];

    float4 r;
    r.x = fmaf(w0, x0.x, fmaf(w1, x0.y, fmaf(w2c, x0.z, fmaf(w3, x0.w, b))));
    r.y = fmaf(w0, x1.x, fmaf(w1, x1.y, fmaf(w2c, x1.z, fmaf(w3, x1.w, b))));
    r.z = fmaf(w0, x2.x, fmaf(w1, x2.y, fmaf(w2c, x2.z, fmaf(w3, x2.w, b))));
    r.w = fmaf(w0, x3.x, fmaf(w1, x3.y, fmaf(w2c, x3.z, fmaf(w3, x3.w, b))));
    __stcs(out + (size_t)img * 65536 + lo4, r);
}

extern "C" void kernel_launch(void* const* d_in, const int* in_sizes, int n_in,
                              void* d_out, int out_size) {
    const float4* in = (const float4*)d_in[0];
    float4* out = (float4*)d_out;
    const int k1_grid = IMGS_PER_GROUP * K1_CTAS_PER_IMG;          // 1024
    const int k3_grid = IMGS_PER_GROUP * 65536 / 256;              // 4096
    for (int g = 0; g < N_GROUPS; g++) {
        const int base = g * IMGS_PER_GROUP;
        k1_group<<<k1_grid, K1_THREADS>>>(in, base);
        k2_group<<<IMGS_PER_GROUP, 64>>>(base);
        k3_group<<<k3_grid, 256>>>(in, out, base);
    }
}

// round 16
// speedup vs baseline: 1.5665x; 1.5665x over previous
#include <cuda_runtime.h>
#include <math.h>

#define N_IMG 32
#define ROWS_PER_IMG 262144              // 128*128*64 / 4 float4-rows per image
#define K1_CTAS_PER_IMG 64
#define K1_THREADS 256
#define ROWS_PER_CTA (ROWS_PER_IMG / K1_CTAS_PER_IMG)   // 4096
#define ROWS_PER_THREAD (ROWS_PER_CTA / K1_THREADS)     // 16
#define K1_BATCH 8

// Deterministic scratch (no device allocation allowed).
__device__ float g_part[N_IMG][K1_CTAS_PER_IMG][14];
__device__ float g_coef[N_IMG][8];   // w0..w3, b, pad

// ---------------------------------------------------------------------------
// K1: per-image raw moments. Every float4 of the image is one patches row.
// EXACT R8 config (measured 25.6us, 5.4TB/s, occ 86%): 2048 CTAs, batch-8.
// ---------------------------------------------------------------------------
__global__ void __launch_bounds__(K1_THREADS) k1_reduce(const float4* __restrict__ in) {
    const int img = blockIdx.x >> 6;
    const int cta = blockIdx.x & 63;
    const float4* p = in + (size_t)img * ROWS_PER_IMG + cta * ROWS_PER_CTA + threadIdx.x;

    float s0 = 0.f, s1 = 0.f, s2 = 0.f, s3 = 0.f;
    float q00 = 0.f, q01 = 0.f, q02 = 0.f, q03 = 0.f;
    float q11 = 0.f, q12 = 0.f, q13 = 0.f;
    float q22 = 0.f, q23 = 0.f, q33 = 0.f;

#pragma unroll
    for (int g = 0; g < ROWS_PER_THREAD / K1_BATCH; g++) {
        float4 buf[K1_BATCH];
#pragma unroll
        for (int j = 0; j < K1_BATCH; j++)
            buf[j] = __ldg(p + (g * K1_BATCH + j) * K1_THREADS);
#pragma unroll
        for (int j = 0; j < K1_BATCH; j++) {
            float4 v = buf[j];
            s0 += v.x; s1 += v.y; s2 += v.z; s3 += v.w;
            q00 = fmaf(v.x, v.x, q00); q01 = fmaf(v.x, v.y, q01);
            q02 = fmaf(v.x, v.z, q02); q03 = fmaf(v.x, v.w, q03);
            q11 = fmaf(v.y, v.y, q11); q12 = fmaf(v.y, v.z, q12);
            q13 = fmaf(v.y, v.w, q13);
            q22 = fmaf(v.z, v.z, q22); q23 = fmaf(v.z, v.w, q23);
            q33 = fmaf(v.w, v.w, q33);
        }
    }

    float vals[14] = {s0, s1, s2, s3, q00, q01, q02, q03, q11, q12, q13, q22, q23, q33};

    __shared__ float sm[8][14];
    const int lane = threadIdx.x & 31;
    const int warp = threadIdx.x >> 5;

#pragma unroll
    for (int i = 0; i < 14; i++) {
        float v = vals[i];
#pragma unroll
        for (int off = 16; off; off >>= 1)
            v += __shfl_down_sync(0xffffffffu, v, off);
        if (lane == 0) sm[warp][i] = v;
    }
    __syncthreads();
    if (warp == 0 && lane < 14) {
        float v = 0.f;
#pragma unroll
        for (int w = 0; w < 8; w++) v += sm[w][lane];
        g_part[img][cta][lane] = v;
    }
}

// ---------------------------------------------------------------------------
// K2: per-image final reduction (fp64, non-iterative), stats, then SHIFTED
// gram E = Gram - N*I in fp64 (cancellation-safe) and Jacobi in fp32 on E
// with a real convergence break. (Unchanged, verified.)
// ---------------------------------------------------------------------------
__global__ void k2_solve() {
    const int img = blockIdx.x;
    const int t = threadIdx.x;
    __shared__ double red[14];

    if (t < 14) {
        double acc = 0.0;
#pragma unroll 4
        for (int c = 0; c < K1_CTAS_PER_IMG; c++)
            acc += (double)g_part[img][c][t];
        red[t] = acc;
    }
    __syncthreads();

    if (t == 0) {
        const double N = (double)ROWS_PER_IMG;
        double S[4] = {red[0], red[1], red[2], red[3]};
        double Q[4][4];
        Q[0][0] = red[4];  Q[0][1] = red[5];  Q[0][2] = red[6];  Q[0][3] = red[7];
        Q[1][1] = red[8];  Q[1][2] = red[9];  Q[1][3] = red[10];
        Q[2][2] = red[11]; Q[2][3] = red[12]; Q[3][3] = red[13];
        Q[1][0] = Q[0][1]; Q[2][0] = Q[0][2]; Q[3][0] = Q[0][3];
        Q[2][1] = Q[1][2]; Q[3][1] = Q[1][3]; Q[3][2] = Q[2][3];

        double mu[4], inv[4];
        bool zerov[4];
#pragma unroll
        for (int i = 0; i < 4; i++) {
            mu[i] = S[i] / N;
            double var = Q[i][i] / N - mu[i] * mu[i];
            if (var < 0.0) var = 0.0;
            double sd = sqrt(var);
            zerov[i] = (sd == 0.0);
            inv[i] = zerov[i] ? 0.0 : 1.0 / sd;
        }

        float A[4][4];
        for (int i = 0; i < 4; i++)
            for (int j = 0; j < 4; j++) {
                double g = (Q[i][j] - N * mu[i] * mu[j]) * inv[i] * inv[j];
                if (i == j) g = zerov[i] ? -N : 0.0;
                A[i][j] = (float)g;
            }

        float V[4][4] = {{1,0,0,0},{0,1,0,0},{0,0,1,0},{0,0,0,1}};
        for (int sweep = 0; sweep < 8; sweep++) {
            float off = fabsf(A[0][1]) + fabsf(A[0][2]) + fabsf(A[0][3])
                      + fabsf(A[1][2]) + fabsf(A[1][3]) + fabsf(A[2][3]);
            if (off < 1e-3f) break;   // entries O(500); fp32 noise floor
            for (int p = 0; p < 3; p++) {
                for (int q = p + 1; q < 4; q++) {
                    float apq = A[p][q];
                    if (fabsf(apq) == 0.0f) continue;
                    float theta = (A[q][q] - A[p][p]) / (2.0f * apq);
                    float tt = ((theta >= 0.0f) ? 1.0f : -1.0f)
                             / (fabsf(theta) + sqrtf(theta * theta + 1.0f));
                    float c = rsqrtf(tt * tt + 1.0f);
                    float s = tt * c;
                    for (int k = 0; k < 4; k++) {
                        float akp = A[k][p], akq = A[k][q];
                        A[k][p] = c * akp - s * akq;
                        A[k][q] = s * akp + c * akq;
                    }
                    for (int k = 0; k < 4; k++) {
                        float apk = A[p][k], aqk = A[q][k];
                        A[p][k] = c * apk - s * aqk;
                        A[q][k] = s * apk + c * aqk;
                    }
                    for (int k = 0; k < 4; k++) {
                        float vkp = V[k][p], vkq = V[k][q];
                        V[k][p] = c * vkp - s * vkq;
                        V[k][q] = s * vkp + c * vkq;
                    }
                }
            }
        }

        int best = 0;
        for (int i = 1; i < 4; i++)
            if (A[i][i] > A[best][best]) best = i;

        float v[4]; float sum = 0.0f;
#pragma unroll
        for (int i = 0; i < 4; i++) { v[i] = V[i][best]; sum += v[i]; }
        double sgn = (sum < 0.0f) ? -1.0 : 1.0;

        double b = 0.0;
#pragma unroll
        for (int i = 0; i < 4; i++) {
            double wi = sgn * (double)v[i] * inv[i];
            g_coef[img][i] = (float)wi;
            b -= wi * mu[i];
        }
        g_coef[img][4] = (float)b;
    }
}

// ---------------------------------------------------------------------------
// K3: projection, 2x-coarsened R8 body: each thread handles output float4s
// at tid and tid+256 of a 512-wide block. Per-instruction access patterns
// identical to R8 (4 consecutive input float4 per output float4, coalesced
// STG.128), but 8 LDG.128 in flight per thread (MLP 4->8), index math
// amortized 2x, grid halved to 4096. Both halves are in the same image
// (65536 % 512 == 0). Reverse traversal + __stcs kept.
// ---------------------------------------------------------------------------
__device__ __forceinline__ float4 k3_body(const float4* __restrict__ in, int o4,
                                          float w0, float w1, float w2c, float w3,
                                          float b) {
    const int lo4 = o4 & 65535;
    const int S  = lo4 >> 4;           // 16 float4 per (h2,w2) block
    const int c4 = lo4 & 15;
    const int h2 = S >> 6, w2i = S & 63;
    const int pp = c4 >> 2;            // ph*2 + pw (4 c_out share a patch pos)
    const int cgb = (c4 & 3) << 2;     // base channel-group 0,4,8,12
    const int ph = pp >> 1, pw = pp & 1;
    const int m = (((h2 << 1) + ph) * 128 + ((w2i << 1) + pw)) * 16 + cgb;

    const float4* src = in + (size_t)(o4 >> 16) * ROWS_PER_IMG + m;
    float4 x0 = __ldg(src + 0);
    float4 x1 = __ldg(src + 1);
    float4 x2 = __ldg(src + 2);
    float4 x3 = __ldg(src + 3);

    float4 r;
    r.x = fmaf(w0, x0.x, fmaf(w1, x0.y, fmaf(w2c, x0.z, fmaf(w3, x0.w, b))));
    r.y = fmaf(w0, x1.x, fmaf(w1, x1.y, fmaf(w2c, x1.z, fmaf(w3, x1.w, b))));
    r.z = fmaf(w0, x2.x, fmaf(w1, x2.y, fmaf(w2c, x2.z, fmaf(w3, x2.w, b))));
    r.w = fmaf(w0, x3.x, fmaf(w1, x3.y, fmaf(w2c, x3.z, fmaf(w3, x3.w, b))));
    return r;
}

__global__ void __launch_bounds__(256) k3_project(const float4* __restrict__ in,
                                                  float4* __restrict__ out) {
    const int blk = gridDim.x - 1 - blockIdx.x;          // reverse traversal
    const int o4a = blk * 512 + threadIdx.x;
    const int o4b = o4a + 256;
    const int img = o4a >> 16;                           // same img for both

    const float* cf = g_coef[img];
    const float w0 = cf[0], w1 = cf[1], w2c = cf[2], w3 = cf[3], b = cf[4];

    float4 ra = k3_body(in, o4a, w0, w1, w2c, w3, b);
    float4 rb = k3_body(in, o4b, w0, w1, w2c, w3, b);
    __stcs(out + o4a, ra);
    __stcs(out + o4b, rb);
}

extern "C" void kernel_launch(void* const* d_in, const int* in_sizes, int n_in,
                              void* d_out, int out_size) {
    const float4* in = (const float4*)d_in[0];
    float4* out = (float4*)d_out;
    k1_reduce<<<N_IMG * K1_CTAS_PER_IMG, K1_THREADS>>>(in);   // 2048 CTAs
    k2_solve<<<N_IMG, 64>>>();
    // 32*65536 float4 outputs / 2 per thread / 256 per block = 4096 blocks
    k3_project<<<(N_IMG * 65536) / 512, 256>>>(in, out);
}

// round 17
// speedup vs baseline: 1.5739x; 1.0047x over previous
#include <cuda_runtime.h>
#include <math.h>

#define N_IMG 32
#define ROWS_PER_IMG 262144              // 128*128*64 / 4 float4-rows per image
#define K1_CTAS_PER_IMG 64
#define K1_THREADS 256
#define ROWS_PER_CTA (ROWS_PER_IMG / K1_CTAS_PER_IMG)   // 4096
#define ROWS_PER_THREAD (ROWS_PER_CTA / K1_THREADS)     // 16
#define K1_BATCH 8

// Deterministic scratch (no device allocation allowed).
__device__ float g_part[N_IMG][K1_CTAS_PER_IMG][14];
__device__ float g_coef[N_IMG][8];   // w0..w3, b, pad

// ---------------------------------------------------------------------------
// K1: per-image raw moments. EXACT proven config (25.7us, 5.37TB/s, occ 91%).
// ---------------------------------------------------------------------------
__global__ void __launch_bounds__(K1_THREADS) k1_reduce(const float4* __restrict__ in) {
    const int img = blockIdx.x >> 6;
    const int cta = blockIdx.x & 63;
    const float4* p = in + (size_t)img * ROWS_PER_IMG + cta * ROWS_PER_CTA + threadIdx.x;

    float s0 = 0.f, s1 = 0.f, s2 = 0.f, s3 = 0.f;
    float q00 = 0.f, q01 = 0.f, q02 = 0.f, q03 = 0.f;
    float q11 = 0.f, q12 = 0.f, q13 = 0.f;
    float q22 = 0.f, q23 = 0.f, q33 = 0.f;

#pragma unroll
    for (int g = 0; g < ROWS_PER_THREAD / K1_BATCH; g++) {
        float4 buf[K1_BATCH];
#pragma unroll
        for (int j = 0; j < K1_BATCH; j++)
            buf[j] = __ldg(p + (g * K1_BATCH + j) * K1_THREADS);
#pragma unroll
        for (int j = 0; j < K1_BATCH; j++) {
            float4 v = buf[j];
            s0 += v.x; s1 += v.y; s2 += v.z; s3 += v.w;
            q00 = fmaf(v.x, v.x, q00); q01 = fmaf(v.x, v.y, q01);
            q02 = fmaf(v.x, v.z, q02); q03 = fmaf(v.x, v.w, q03);
            q11 = fmaf(v.y, v.y, q11); q12 = fmaf(v.y, v.z, q12);
            q13 = fmaf(v.y, v.w, q13);
            q22 = fmaf(v.z, v.z, q22); q23 = fmaf(v.z, v.w, q23);
            q33 = fmaf(v.w, v.w, q33);
        }
    }

    float vals[14] = {s0, s1, s2, s3, q00, q01, q02, q03, q11, q12, q13, q22, q23, q33};

    __shared__ float sm[8][14];
    const int lane = threadIdx.x & 31;
    const int warp = threadIdx.x >> 5;

#pragma unroll
    for (int i = 0; i < 14; i++) {
        float v = vals[i];
#pragma unroll
        for (int off = 16; off; off >>= 1)
            v += __shfl_down_sync(0xffffffffu, v, off);
        if (lane == 0) sm[warp][i] = v;
    }
    __syncthreads();
    if (warp == 0 && lane < 14) {
        float v = 0.f;
#pragma unroll
        for (int w = 0; w < 8; w++) v += sm[w][lane];
        g_part[img][cta][lane] = v;
    }
}

// ---------------------------------------------------------------------------
// K2: launched with PDL — begins while K1 drains; gridDepSync before touching
// g_part (full visibility at K1 completion). Math unchanged (verified):
// fp64 reduction + stats, shifted gram E = Gram - N*I, fp32 Jacobi on E.
// ---------------------------------------------------------------------------
__global__ void k2_solve() {
    cudaGridDependencySynchronize();

    const int img = blockIdx.x;
    const int t = threadIdx.x;
    __shared__ double red[14];

    if (t < 14) {
        double acc = 0.0;
#pragma unroll 4
        for (int c = 0; c < K1_CTAS_PER_IMG; c++)
            acc += (double)g_part[img][c][t];
        red[t] = acc;
    }
    __syncthreads();

    if (t == 0) {
        const double N = (double)ROWS_PER_IMG;
        double S[4] = {red[0], red[1], red[2], red[3]};
        double Q[4][4];
        Q[0][0] = red[4];  Q[0][1] = red[5];  Q[0][2] = red[6];  Q[0][3] = red[7];
        Q[1][1] = red[8];  Q[1][2] = red[9];  Q[1][3] = red[10];
        Q[2][2] = red[11]; Q[2][3] = red[12]; Q[3][3] = red[13];
        Q[1][0] = Q[0][1]; Q[2][0] = Q[0][2]; Q[3][0] = Q[0][3];
        Q[2][1] = Q[1][2]; Q[3][1] = Q[1][3]; Q[3][2] = Q[2][3];

        double mu[4], inv[4];
        bool zerov[4];
#pragma unroll
        for (int i = 0; i < 4; i++) {
            mu[i] = S[i] / N;
            double var = Q[i][i] / N - mu[i] * mu[i];
            if (var < 0.0) var = 0.0;
            double sd = sqrt(var);
            zerov[i] = (sd == 0.0);
            inv[i] = zerov[i] ? 0.0 : 1.0 / sd;
        }

        float A[4][4];
        for (int i = 0; i < 4; i++)
            for (int j = 0; j < 4; j++) {
                double g = (Q[i][j] - N * mu[i] * mu[j]) * inv[i] * inv[j];
                if (i == j) g = zerov[i] ? -N : 0.0;
                A[i][j] = (float)g;
            }

        float V[4][4] = {{1,0,0,0},{0,1,0,0},{0,0,1,0},{0,0,0,1}};
        for (int sweep = 0; sweep < 8; sweep++) {
            float off = fabsf(A[0][1]) + fabsf(A[0][2]) + fabsf(A[0][3])
                      + fabsf(A[1][2]) + fabsf(A[1][3]) + fabsf(A[2][3]);
            if (off < 1e-3f) break;   // entries O(500); fp32 noise floor
            for (int p = 0; p < 3; p++) {
                for (int q = p + 1; q < 4; q++) {
                    float apq = A[p][q];
                    if (fabsf(apq) == 0.0f) continue;
                    float theta = (A[q][q] - A[p][p]) / (2.0f * apq);
                    float tt = ((theta >= 0.0f) ? 1.0f : -1.0f)
                             / (fabsf(theta) + sqrtf(theta * theta + 1.0f));
                    float c = rsqrtf(tt * tt + 1.0f);
                    float s = tt * c;
                    for (int k = 0; k < 4; k++) {
                        float akp = A[k][p], akq = A[k][q];
                        A[k][p] = c * akp - s * akq;
                        A[k][q] = s * akp + c * akq;
                    }
                    for (int k = 0; k < 4; k++) {
                        float apk = A[p][k], aqk = A[q][k];
                        A[p][k] = c * apk - s * aqk;
                        A[q][k] = s * apk + c * aqk;
                    }
                    for (int k = 0; k < 4; k++) {
                        float vkp = V[k][p], vkq = V[k][q];
                        V[k][p] = c * vkp - s * vkq;
                        V[k][q] = s * vkp + c * vkq;
                    }
                }
            }
        }

        int best = 0;
        for (int i = 1; i < 4; i++)
            if (A[i][i] > A[best][best]) best = i;

        float v[4]; float sum = 0.0f;
#pragma unroll
        for (int i = 0; i < 4; i++) { v[i] = V[i][best]; sum += v[i]; }
        double sgn = (sum < 0.0f) ? -1.0 : 1.0;

        double b = 0.0;
#pragma unroll
        for (int i = 0; i < 4; i++) {
            double wi = sgn * (double)v[i] * inv[i];
            g_coef[img][i] = (float)wi;
            b -= wi * mu[i];
        }
        g_coef[img][4] = (float)b;
    }
}

// ---------------------------------------------------------------------------
// K3: launched with PDL. The input loads do NOT depend on K2's output, so
// each thread issues all 8 LDG.128 BEFORE cudaGridDependencySynchronize() —
// the first resident wave overlaps its read stream with K2's execution and
// the launch gap. Only the g_coef read + FMA + store follow the sync.
// Body otherwise identical to the proven 2x-coarsened version.
// ---------------------------------------------------------------------------
__device__ __forceinline__ int k3_src_index(int o4) {
    const int lo4 = o4 & 65535;
    const int S  = lo4 >> 4;           // 16 float4 per (h2,w2) block
    const int c4 = lo4 & 15;
    const int h2 = S >> 6, w2i = S & 63;
    const int pp = c4 >> 2;            // ph*2 + pw (4 c_out share a patch pos)
    const int cgb = (c4 & 3) << 2;     // base channel-group 0,4,8,12
    const int ph = pp >> 1, pw = pp & 1;
    return (((h2 << 1) + ph) * 128 + ((w2i << 1) + pw)) * 16 + cgb;
}

__global__ void __launch_bounds__(256) k3_project(const float4* __restrict__ in,
                                                  float4* __restrict__ out) {
    const int blk = gridDim.x - 1 - blockIdx.x;          // reverse traversal
    const int o4a = blk * 512 + threadIdx.x;
    const int o4b = o4a + 256;
    const int img = o4a >> 16;                           // same img for both

    const float4* srca = in + (size_t)img * ROWS_PER_IMG + k3_src_index(o4a);
    const float4* srcb = in + (size_t)img * ROWS_PER_IMG + k3_src_index(o4b);

    // Issue all input loads before the dependency sync (independent of K2).
    float4 a0 = __ldg(srca + 0), a1 = __ldg(srca + 1);
    float4 a2 = __ldg(srca + 2), a3 = __ldg(srca + 3);
    float4 b0 = __ldg(srcb + 0), b1 = __ldg(srcb + 1);
    float4 b2 = __ldg(srcb + 2), b3 = __ldg(srcb + 3);

    cudaGridDependencySynchronize();

    const float* cf = g_coef[img];
    const float w0 = cf[0], w1 = cf[1], w2c = cf[2], w3 = cf[3], bb = cf[4];

    float4 ra, rb;
    ra.x = fmaf(w0, a0.x, fmaf(w1, a0.y, fmaf(w2c, a0.z, fmaf(w3, a0.w, bb))));
    ra.y = fmaf(w0, a1.x, fmaf(w1, a1.y, fmaf(w2c, a1.z, fmaf(w3, a1.w, bb))));
    ra.z = fmaf(w0, a2.x, fmaf(w1, a2.y, fmaf(w2c, a2.z, fmaf(w3, a2.w, bb))));
    ra.w = fmaf(w0, a3.x, fmaf(w1, a3.y, fmaf(w2c, a3.z, fmaf(w3, a3.w, bb))));
    rb.x = fmaf(w0, b0.x, fmaf(w1, b0.y, fmaf(w2c, b0.z, fmaf(w3, b0.w, bb))));
    rb.y = fmaf(w0, b1.x, fmaf(w1, b1.y, fmaf(w2c, b1.z, fmaf(w3, b1.w, bb))));
    rb.z = fmaf(w0, b2.x, fmaf(w1, b2.y, fmaf(w2c, b2.z, fmaf(w3, b2.w, bb))));
    rb.w = fmaf(w0, b3.x, fmaf(w1, b3.y, fmaf(w2c, b3.z, fmaf(w3, b3.w, bb))));
    __stcs(out + o4a, ra);
    __stcs(out + o4b, rb);
}

extern "C" void kernel_launch(void* const* d_in, const int* in_sizes, int n_in,
                              void* d_out, int out_size) {
    const float4* in = (const float4*)d_in[0];
    float4* out = (float4*)d_out;

    k1_reduce<<<N_IMG * K1_CTAS_PER_IMG, K1_THREADS>>>(in);   // 2048 CTAs

    cudaLaunchAttribute pdl[1];
    pdl[0].id = cudaLaunchAttributeProgrammaticStreamSerialization;
    pdl[0].val.programmaticStreamSerializationAllowed = 1;

    {   // K2 with PDL over K1
        cudaLaunchConfig_t cfg = {};
        cfg.gridDim = dim3(N_IMG, 1, 1);
        cfg.blockDim = dim3(64, 1, 1);
        cfg.stream = 0;
        cfg.attrs = pdl;
        cfg.numAttrs = 1;
        cudaLaunchKernelEx(&cfg, k2_solve);
    }
    {   // K3 with PDL over K2 — loads overlap K2 + launch gap
        cudaLaunchConfig_t cfg = {};
        cfg.gridDim = dim3((N_IMG * 65536) / 512, 1, 1);      // 4096 blocks
        cfg.blockDim = dim3(256, 1, 1);
        cfg.stream = 0;
        cfg.attrs = pdl;
        cfg.numAttrs = 1;
        cudaLaunchKernelEx(&cfg, k3_project, in, out);
    }
}